// round 1
// baseline (speedup 1.0000x reference)
#include <cuda_runtime.h>
#include <math.h>

#define Nn   32
#define Cc   192
#define Tt   256
#define Vv   25
#define Ss   3
#define MID  64
#define TV   (Tt * Vv)      /* 6400 */
#define C3   (3 * Cc)       /* 576  */

// Scratch (static device arrays; allocation-free per harness rules)
__device__ float g_qkv[(size_t)Nn * C3 * TV];      // ~472 MB
__device__ float g_att[(size_t)Nn * Ss * Tt * Tt]; // ~25 MB
__device__ float g_y[(size_t)Nn * Cc * TV];        // ~157 MB

// ---------------------------------------------------------------------------
// Kernel 1: QKV projection.  qkv[n,d,tv] = sum_c w_in[d,c] * x[n,c,tv] + b_in[d]
// GEMM per n: (576 x 192) @ (192 x 6400). Tile 64x64, BK=16, 4x4 micro-tile.
// ---------------------------------------------------------------------------
__global__ __launch_bounds__(256) void k_qkv(const float* __restrict__ x,
                                             const float* __restrict__ w_in,
                                             const float* __restrict__ b_in) {
    __shared__ float As[16][64];  // As[k][d]
    __shared__ float Bs[16][64];  // Bs[k][tv]
    const int n  = blockIdx.z;
    const int d0 = blockIdx.y * 64;
    const int p0 = blockIdx.x * 64;
    const int tid = threadIdx.x;
    const int tx = tid & 15, ty = tid >> 4;

    const float* xn = x + (size_t)n * Cc * TV;
    float acc[4][4] = {};

    const int am = tid >> 2;          // 0..63 : d row within tile
    const int ak = (tid & 3) * 4;     // k base for A load
    const int bk = tid >> 4;          // 0..15 : k row for B load
    const int bp = (tid & 15) * 4;    // col base for B load

    for (int k0 = 0; k0 < Cc; k0 += 16) {
        float4 av = *(const float4*)&w_in[(size_t)(d0 + am) * Cc + k0 + ak];
        As[ak + 0][am] = av.x; As[ak + 1][am] = av.y;
        As[ak + 2][am] = av.z; As[ak + 3][am] = av.w;
        *(float4*)&Bs[bk][bp] =
            *(const float4*)&xn[(size_t)(k0 + bk) * TV + p0 + bp];
        __syncthreads();
#pragma unroll
        for (int k = 0; k < 16; k++) {
            float4 ra = *(float4*)&As[k][ty * 4];
            float4 rb = *(float4*)&Bs[k][tx * 4];
            float a_[4] = {ra.x, ra.y, ra.z, ra.w};
            float b_[4] = {rb.x, rb.y, rb.z, rb.w};
#pragma unroll
            for (int i = 0; i < 4; i++)
#pragma unroll
                for (int j = 0; j < 4; j++)
                    acc[i][j] = fmaf(a_[i], b_[j], acc[i][j]);
        }
        __syncthreads();
    }

    float* out = g_qkv + (size_t)n * C3 * TV;
#pragma unroll
    for (int i = 0; i < 4; i++) {
        const int d = d0 + ty * 4 + i;
        const float bias = b_in[d];
        float4 r = make_float4(acc[i][0] + bias, acc[i][1] + bias,
                               acc[i][2] + bias, acc[i][3] + bias);
        *(float4*)&out[(size_t)d * TV + p0 + tx * 4] = r;
    }
}

// ---------------------------------------------------------------------------
// Kernel 2: attention scores.
// att[n,s,t,q] = tanh( sum_{c,v} Q[n,s,c,t,v]*K[n,s,c,q,v] / (mid*V) )
// Per block: one (n,s), 64x64 tile of (t,q), loop c=0..63, inner v=0..24.
// ---------------------------------------------------------------------------
__global__ __launch_bounds__(256) void k_att() {
    __shared__ float Qs[25][72];  // [v][t], stride 72 (16B-aligned rows)
    __shared__ float Ks[25][72];  // [v][q]
    const int ns = blockIdx.z;              // n*3 + s
    const int n = ns / 3, s = ns - 3 * n;
    const int t0 = blockIdx.y * 64;
    const int q0 = blockIdx.x * 64;
    const int tid = threadIdx.x;
    const int tx = tid & 15, ty = tid >> 4;

    const float* qbase = g_qkv + ((size_t)n * C3 + s * MID) * TV;
    const float* kbase = g_qkv + ((size_t)n * C3 + Ss * MID + s * MID) * TV;

    float acc[4][4] = {};

    for (int c = 0; c < MID; c++) {
        const float* qc = qbase + (size_t)c * TV;
        const float* kc = kbase + (size_t)c * TV;
        for (int idx = tid; idx < 64 * 25; idx += 256) {
            const int t = idx / 25;
            const int v = idx - t * 25;
            Qs[v][t] = qc[(t0 + t) * Vv + v];
            Ks[v][t] = kc[(q0 + t) * Vv + v];
        }
        __syncthreads();
#pragma unroll
        for (int v = 0; v < 25; v++) {
            float4 ra = *(float4*)&Qs[v][ty * 4];
            float4 rb = *(float4*)&Ks[v][tx * 4];
            float a_[4] = {ra.x, ra.y, ra.z, ra.w};
            float b_[4] = {rb.x, rb.y, rb.z, rb.w};
#pragma unroll
            for (int i = 0; i < 4; i++)
#pragma unroll
                for (int j = 0; j < 4; j++)
                    acc[i][j] = fmaf(a_[i], b_[j], acc[i][j]);
        }
        __syncthreads();
    }

    const float scale = 1.0f / (float)(MID * Vv);
    float* att = g_att + ((size_t)ns * Tt + t0) * Tt + q0;
#pragma unroll
    for (int i = 0; i < 4; i++)
#pragma unroll
        for (int j = 0; j < 4; j++)
            att[(size_t)(ty * 4 + i) * Tt + tx * 4 + j] =
                tanhf(acc[i][j] * scale);
}

// ---------------------------------------------------------------------------
// Kernel 3: y[n, s*64+c, t, v] = sum_q att[n,s,t,q] * V[n,s,c,q,v]
// Per (n,s): GEMM (256 x 256) @ (256 x 1600) with cols j = c*25+v.
// Tile 64(t) x 64(j), BK=32.
// ---------------------------------------------------------------------------
__global__ __launch_bounds__(256) void k_y() {
    __shared__ float As[32][64];  // As[q][t]
    __shared__ float Bs[32][64];  // Bs[q][j]
    const int ns = blockIdx.z;
    const int n = ns / 3, s = ns - 3 * n;
    const int t0 = blockIdx.y * 64;
    const int j0 = blockIdx.x * 64;
    const int tid = threadIdx.x;
    const int tx = tid & 15, ty = tid >> 4;

    const float* att   = g_att + (size_t)ns * Tt * Tt;
    const float* vbase = g_qkv + ((size_t)n * C3 + 2 * Ss * MID + s * MID) * TV;

    float acc[4][4] = {};

    const int at = tid >> 2;          // 0..63 : t row
    const int aq = (tid & 3) * 8;     // q base (two float4)
    const int bq = tid >> 3;          // 0..31 : q row
    const int bj = (tid & 7) * 8;     // j base (8 scalars)

    for (int q0 = 0; q0 < Tt; q0 += 32) {
        float4 a0 = *(const float4*)&att[(size_t)(t0 + at) * Tt + q0 + aq];
        float4 a1 = *(const float4*)&att[(size_t)(t0 + at) * Tt + q0 + aq + 4];
        As[aq + 0][at] = a0.x; As[aq + 1][at] = a0.y;
        As[aq + 2][at] = a0.z; As[aq + 3][at] = a0.w;
        As[aq + 4][at] = a1.x; As[aq + 5][at] = a1.y;
        As[aq + 6][at] = a1.z; As[aq + 7][at] = a1.w;
#pragma unroll
        for (int l = 0; l < 8; l++) {
            const int jj = j0 + bj + l;
            const int c = jj / 25;
            const int v = jj - c * 25;
            Bs[bq][bj + l] = vbase[((size_t)c * Tt + q0 + bq) * Vv + v];
        }
        __syncthreads();
#pragma unroll
        for (int k = 0; k < 32; k++) {
            float4 ra = *(float4*)&As[k][ty * 4];
            float4 rb = *(float4*)&Bs[k][tx * 4];
            float a_[4] = {ra.x, ra.y, ra.z, ra.w};
            float b_[4] = {rb.x, rb.y, rb.z, rb.w};
#pragma unroll
            for (int i = 0; i < 4; i++)
#pragma unroll
                for (int j = 0; j < 4; j++)
                    acc[i][j] = fmaf(a_[i], b_[j], acc[i][j]);
        }
        __syncthreads();
    }

    float* yn = g_y + (size_t)n * Cc * TV;
#pragma unroll
    for (int i = 0; i < 4; i++)
#pragma unroll
        for (int j = 0; j < 4; j++) {
            const int jj = j0 + tx * 4 + j;
            const int c = jj / 25;
            const int v = jj - c * 25;
            yn[((size_t)(s * MID + c) * Tt + (t0 + ty * 4 + i)) * Vv + v] =
                acc[i][j];
        }
}

// ---------------------------------------------------------------------------
// Kernel 4: FF + BatchNorm + residual + LeakyReLU(0.1)
// out[n,d,tv] = leaky( x[n,d,tv] + ((ff_y - mean)*inv + beta) )
// GEMM per n: (192 x 192) @ (192 x 6400), fused epilogue.
// ---------------------------------------------------------------------------
__global__ __launch_bounds__(256) void k_ff(const float* __restrict__ x,
                                            const float* __restrict__ w_ff,
                                            const float* __restrict__ b_ff,
                                            const float* __restrict__ gamma,
                                            const float* __restrict__ beta,
                                            const float* __restrict__ mean,
                                            const float* __restrict__ var,
                                            float* __restrict__ out) {
    __shared__ float As[16][64];
    __shared__ float Bs[16][64];
    const int n  = blockIdx.z;
    const int d0 = blockIdx.y * 64;
    const int p0 = blockIdx.x * 64;
    const int tid = threadIdx.x;
    const int tx = tid & 15, ty = tid >> 4;

    const float* yn = g_y + (size_t)n * Cc * TV;
    float acc[4][4] = {};

    const int am = tid >> 2;
    const int ak = (tid & 3) * 4;
    const int bk = tid >> 4;
    const int bp = (tid & 15) * 4;

    for (int k0 = 0; k0 < Cc; k0 += 16) {
        float4 av = *(const float4*)&w_ff[(size_t)(d0 + am) * Cc + k0 + ak];
        As[ak + 0][am] = av.x; As[ak + 1][am] = av.y;
        As[ak + 2][am] = av.z; As[ak + 3][am] = av.w;
        *(float4*)&Bs[bk][bp] =
            *(const float4*)&yn[(size_t)(k0 + bk) * TV + p0 + bp];
        __syncthreads();
#pragma unroll
        for (int k = 0; k < 16; k++) {
            float4 ra = *(float4*)&As[k][ty * 4];
            float4 rb = *(float4*)&Bs[k][tx * 4];
            float a_[4] = {ra.x, ra.y, ra.z, ra.w};
            float b_[4] = {rb.x, rb.y, rb.z, rb.w};
#pragma unroll
            for (int i = 0; i < 4; i++)
#pragma unroll
                for (int j = 0; j < 4; j++)
                    acc[i][j] = fmaf(a_[i], b_[j], acc[i][j]);
        }
        __syncthreads();
    }

    const float* xn = x + (size_t)n * Cc * TV;
#pragma unroll
    for (int i = 0; i < 4; i++) {
        const int d = d0 + ty * 4 + i;
        const float inv = gamma[d] * rsqrtf(var[d] + 1e-5f);
        const float add = (b_ff[d] - mean[d]) * inv + beta[d];
        const size_t off = (size_t)d * TV + p0 + tx * 4;
        float4 xv = *(const float4*)&xn[off];
        float zv[4];
        zv[0] = xv.x + acc[i][0] * inv + add;
        zv[1] = xv.y + acc[i][1] * inv + add;
        zv[2] = xv.z + acc[i][2] * inv + add;
        zv[3] = xv.w + acc[i][3] * inv + add;
        float4 r;
        r.x = zv[0] >= 0.f ? zv[0] : 0.1f * zv[0];
        r.y = zv[1] >= 0.f ? zv[1] : 0.1f * zv[1];
        r.z = zv[2] >= 0.f ? zv[2] : 0.1f * zv[2];
        r.w = zv[3] >= 0.f ? zv[3] : 0.1f * zv[3];
        *(float4*)&out[(size_t)n * Cc * TV + off] = r;
    }
}

// ---------------------------------------------------------------------------
extern "C" void kernel_launch(void* const* d_in, const int* in_sizes, int n_in,
                              void* d_out, int out_size) {
    (void)in_sizes; (void)n_in; (void)out_size;
    const float* x     = (const float*)d_in[0];
    const float* w_in  = (const float*)d_in[1];
    const float* b_in  = (const float*)d_in[2];
    const float* w_ff  = (const float*)d_in[3];
    const float* b_ff  = (const float*)d_in[4];
    const float* gamma = (const float*)d_in[5];
    const float* beta  = (const float*)d_in[6];
    const float* mean  = (const float*)d_in[7];
    const float* var   = (const float*)d_in[8];
    float* out = (float*)d_out;

    k_qkv<<<dim3(TV / 64, C3 / 64, Nn), 256>>>(x, w_in, b_in);
    k_att<<<dim3(Tt / 64, Tt / 64, Nn * Ss), 256>>>();
    k_y  <<<dim3((MID * Vv) / 64, Tt / 64, Nn * Ss), 256>>>();
    k_ff <<<dim3(TV / 64, Cc / 64, Nn), 256>>>(x, w_ff, b_ff, gamma, beta,
                                               mean, var, out);
}

// round 2
// speedup vs baseline: 1.1301x; 1.1301x over previous
#include <cuda_runtime.h>
#include <math.h>

#define Nn   32
#define Cc   192
#define Tt   256
#define Vv   25
#define Ss   3
#define MID  64
#define TV   (Tt * Vv)      /* 6400 */
#define C3   (3 * Cc)       /* 576  */

// Scratch (static device arrays; allocation-free per harness rules)
__device__ float g_qkv[(size_t)Nn * C3 * TV];      // ~472 MB
__device__ float g_att[(size_t)Nn * Ss * Tt * Tt]; // ~25 MB
__device__ float g_y[(size_t)Nn * Cc * TV];        // ~157 MB

// ---------------------------------------------------------------------------
// Kernel 1: QKV projection.  qkv[n,d,tv] = sum_c w_in[d,c]*x[n,c,tv] + b_in[d]
// GEMM per n: (576 x 192) @ (192 x 6400). Tile M=64(d) x N=128(tv), BK=16,
// 128 threads, 8x8 micro-tile (split fragments for bank-free LDS.128).
// ---------------------------------------------------------------------------
__global__ __launch_bounds__(128) void k_qkv(const float* __restrict__ x,
                                             const float* __restrict__ w_in,
                                             const float* __restrict__ b_in) {
    __shared__ float As[16][68];   // [k][d], padded
    __shared__ float Bs[16][128];  // [k][tv]
    const int n  = blockIdx.z;
    const int d0 = blockIdx.y * 64;
    const int p0 = blockIdx.x * 128;
    const int tid  = threadIdx.x;
    const int trow = tid >> 4;     // 0..7  -> rows trow*4, 32+trow*4
    const int tcol = tid & 15;     // 0..15 -> cols tcol*4, 64+tcol*4

    const float* xn = x + (size_t)n * Cc * TV;
    float acc[8][8] = {};

    const int am = tid >> 1;            // 0..63 : d row
    const int kq = (tid & 1) * 8;       // k base for A (two float4)
    const int bk = tid >> 3;            // 0..15 : k row for B
    const int bp = (tid & 7) * 16;      // col base for B (4 float4)

    for (int k0 = 0; k0 < Cc; k0 += 16) {
        float4 a0 = *(const float4*)&w_in[(size_t)(d0 + am) * Cc + k0 + kq];
        float4 a1 = *(const float4*)&w_in[(size_t)(d0 + am) * Cc + k0 + kq + 4];
        As[kq + 0][am] = a0.x; As[kq + 1][am] = a0.y;
        As[kq + 2][am] = a0.z; As[kq + 3][am] = a0.w;
        As[kq + 4][am] = a1.x; As[kq + 5][am] = a1.y;
        As[kq + 6][am] = a1.z; As[kq + 7][am] = a1.w;
        const float* src = &xn[(size_t)(k0 + bk) * TV + p0 + bp];
        *(float4*)&Bs[bk][bp + 0]  = *(const float4*)&src[0];
        *(float4*)&Bs[bk][bp + 4]  = *(const float4*)&src[4];
        *(float4*)&Bs[bk][bp + 8]  = *(const float4*)&src[8];
        *(float4*)&Bs[bk][bp + 12] = *(const float4*)&src[12];
        __syncthreads();
#pragma unroll
        for (int k = 0; k < 16; k++) {
            float4 ra0 = *(float4*)&As[k][trow * 4];
            float4 ra1 = *(float4*)&As[k][32 + trow * 4];
            float4 rb0 = *(float4*)&Bs[k][tcol * 4];
            float4 rb1 = *(float4*)&Bs[k][64 + tcol * 4];
            float a_[8] = {ra0.x, ra0.y, ra0.z, ra0.w, ra1.x, ra1.y, ra1.z, ra1.w};
            float b_[8] = {rb0.x, rb0.y, rb0.z, rb0.w, rb1.x, rb1.y, rb1.z, rb1.w};
#pragma unroll
            for (int i = 0; i < 8; i++)
#pragma unroll
                for (int j = 0; j < 8; j++)
                    acc[i][j] = fmaf(a_[i], b_[j], acc[i][j]);
        }
        __syncthreads();
    }

    float* out = g_qkv + (size_t)n * C3 * TV;
#pragma unroll
    for (int h = 0; h < 2; h++)
#pragma unroll
        for (int i = 0; i < 4; i++) {
            const int d = d0 + h * 32 + trow * 4 + i;
            const float bias = b_in[d];
            const int r = h * 4 + i;
#pragma unroll
            for (int g = 0; g < 2; g++) {
                float4 v = make_float4(acc[r][g * 4 + 0] + bias,
                                       acc[r][g * 4 + 1] + bias,
                                       acc[r][g * 4 + 2] + bias,
                                       acc[r][g * 4 + 3] + bias);
                *(float4*)&out[(size_t)d * TV + p0 + g * 64 + tcol * 4] = v;
            }
        }
}

// ---------------------------------------------------------------------------
// Kernel 2: attention scores.
// att[n,s,t,q] = tanh( sum_{c,v} Q[n,s,c,t,v]*K[n,s,c,q,v] / (mid*V) )
// Tile M=64(t) x N=128(q), loop c (64), inner v (25), 8x8 micro-tile.
// ---------------------------------------------------------------------------
__global__ __launch_bounds__(128) void k_att() {
    __shared__ float Qs[25][68];   // [v][t]
    __shared__ float Ks[25][136];  // [v][q]
    const int ns = blockIdx.z;
    const int n = ns / 3, s = ns - 3 * n;
    const int t0 = blockIdx.y * 64;
    const int q0 = blockIdx.x * 128;
    const int tid  = threadIdx.x;
    const int trow = tid >> 4;   // 0..7
    const int tcol = tid & 15;   // 0..15

    const float* qbase = g_qkv + ((size_t)n * C3 + s * MID) * TV + (size_t)t0 * Vv;
    const float* kbase = g_qkv + ((size_t)n * C3 + Ss * MID + s * MID) * TV + (size_t)q0 * Vv;

    float acc[8][8] = {};

    for (int c = 0; c < MID; c++) {
        const float* qc = qbase + (size_t)c * TV;
        const float* kc = kbase + (size_t)c * TV;
        for (int idx = tid; idx < 64 * Vv; idx += 128) {
            const int t = idx / 25, v = idx - t * 25;
            Qs[v][t] = qc[idx];
        }
        for (int idx = tid; idx < 128 * Vv; idx += 128) {
            const int t = idx / 25, v = idx - t * 25;
            Ks[v][t] = kc[idx];
        }
        __syncthreads();
#pragma unroll
        for (int v = 0; v < 25; v++) {
            float4 ra0 = *(float4*)&Qs[v][trow * 4];
            float4 ra1 = *(float4*)&Qs[v][32 + trow * 4];
            float4 rb0 = *(float4*)&Ks[v][tcol * 4];
            float4 rb1 = *(float4*)&Ks[v][64 + tcol * 4];
            float a_[8] = {ra0.x, ra0.y, ra0.z, ra0.w, ra1.x, ra1.y, ra1.z, ra1.w};
            float b_[8] = {rb0.x, rb0.y, rb0.z, rb0.w, rb1.x, rb1.y, rb1.z, rb1.w};
#pragma unroll
            for (int i = 0; i < 8; i++)
#pragma unroll
                for (int j = 0; j < 8; j++)
                    acc[i][j] = fmaf(a_[i], b_[j], acc[i][j]);
        }
        __syncthreads();
    }

    const float scale = 1.0f / (float)(MID * Vv);
    float* att = g_att + (size_t)ns * Tt * Tt;
#pragma unroll
    for (int h = 0; h < 2; h++)
#pragma unroll
        for (int i = 0; i < 4; i++) {
            const int t = t0 + h * 32 + trow * 4 + i;
            const int r = h * 4 + i;
#pragma unroll
            for (int g = 0; g < 2; g++) {
                float4 v = make_float4(tanhf(acc[r][g * 4 + 0] * scale),
                                       tanhf(acc[r][g * 4 + 1] * scale),
                                       tanhf(acc[r][g * 4 + 2] * scale),
                                       tanhf(acc[r][g * 4 + 3] * scale));
                *(float4*)&att[(size_t)t * Tt + q0 + g * 64 + tcol * 4] = v;
            }
        }
}

// ---------------------------------------------------------------------------
// Kernel 3: y[n, s*64+c, t, v] = sum_q att[n,s,t,q] * V[n,s,c,q,v]
// Per (n,s): GEMM (256t x 256q) @ (256q x 1600j), j=c*25+v.
// Tile M=128(t) x N=64(j), BK=32, 128 threads, 8x8 micro-tile.
// ---------------------------------------------------------------------------
__global__ __launch_bounds__(128) void k_y() {
    __shared__ float As[32][132];  // [q][t], padded
    __shared__ float Bs[32][64];   // [q][j]
    const int ns = blockIdx.z;
    const int n = ns / 3, s = ns - 3 * n;
    const int t0 = blockIdx.y * 128;
    const int j0 = blockIdx.x * 64;
    const int tid  = threadIdx.x;
    const int trow = tid >> 3;   // 0..15 -> rows trow*4, 64+trow*4
    const int tcol = tid & 7;    // 0..7  -> cols tcol*4, 32+tcol*4

    const float* att   = g_att + (size_t)ns * Tt * Tt;
    const float* vbase = g_qkv + ((size_t)n * C3 + 2 * Ss * MID + s * MID) * TV;

    float acc[8][8] = {};

    for (int qk = 0; qk < Tt; qk += 32) {
        // A transpose-load: row t=tid, 8 float4 along q
        const float* arow = &att[(size_t)(t0 + tid) * Tt + qk];
#pragma unroll
        for (int u = 0; u < 8; u++) {
            float4 v = *(const float4*)&arow[u * 4];
            As[u * 4 + 0][tid] = v.x; As[u * 4 + 1][tid] = v.y;
            As[u * 4 + 2][tid] = v.z; As[u * 4 + 3][tid] = v.w;
        }
        // B: 32q x 64j scalars
#pragma unroll
        for (int l = 0; l < 16; l++) {
            const int idx = l * 128 + tid;
            const int q = idx >> 6, j = idx & 63;
            const int jj = j0 + j;
            const int c = jj / 25, v = jj - c * 25;
            Bs[q][j] = vbase[((size_t)c * Tt + qk + q) * Vv + v];
        }
        __syncthreads();
#pragma unroll
        for (int k = 0; k < 32; k++) {
            float4 ra0 = *(float4*)&As[k][trow * 4];
            float4 ra1 = *(float4*)&As[k][64 + trow * 4];
            float4 rb0 = *(float4*)&Bs[k][tcol * 4];
            float4 rb1 = *(float4*)&Bs[k][32 + tcol * 4];
            float a_[8] = {ra0.x, ra0.y, ra0.z, ra0.w, ra1.x, ra1.y, ra1.z, ra1.w};
            float b_[8] = {rb0.x, rb0.y, rb0.z, rb0.w, rb1.x, rb1.y, rb1.z, rb1.w};
#pragma unroll
            for (int i = 0; i < 8; i++)
#pragma unroll
                for (int j = 0; j < 8; j++)
                    acc[i][j] = fmaf(a_[i], b_[j], acc[i][j]);
        }
        __syncthreads();
    }

    float* yn = g_y + (size_t)n * Cc * TV;
#pragma unroll
    for (int h = 0; h < 2; h++)
#pragma unroll
        for (int i = 0; i < 4; i++) {
            const int t = t0 + h * 64 + trow * 4 + i;
            const int r = h * 4 + i;
#pragma unroll
            for (int g = 0; g < 2; g++)
#pragma unroll
                for (int j = 0; j < 4; j++) {
                    const int jj = j0 + g * 32 + tcol * 4 + j;
                    const int c = jj / 25, v = jj - c * 25;
                    yn[((size_t)(s * MID + c) * Tt + t) * Vv + v] =
                        acc[r][g * 4 + j];
                }
        }
}

// ---------------------------------------------------------------------------
// Kernel 4: FF + BatchNorm + residual + LeakyReLU(0.1)
// GEMM per n: (192 x 192) @ (192 x 6400), fused epilogue.
// Tile M=64(d) x N=128(tv), BK=16, 128 threads, 8x8 micro-tile.
// ---------------------------------------------------------------------------
__global__ __launch_bounds__(128) void k_ff(const float* __restrict__ x,
                                            const float* __restrict__ w_ff,
                                            const float* __restrict__ b_ff,
                                            const float* __restrict__ gamma,
                                            const float* __restrict__ beta,
                                            const float* __restrict__ mean,
                                            const float* __restrict__ var,
                                            float* __restrict__ out) {
    __shared__ float As[16][68];
    __shared__ float Bs[16][128];
    const int n  = blockIdx.z;
    const int d0 = blockIdx.y * 64;
    const int p0 = blockIdx.x * 128;
    const int tid  = threadIdx.x;
    const int trow = tid >> 4;
    const int tcol = tid & 15;

    const float* yn = g_y + (size_t)n * Cc * TV;
    float acc[8][8] = {};

    const int am = tid >> 1;
    const int kq = (tid & 1) * 8;
    const int bk = tid >> 3;
    const int bp = (tid & 7) * 16;

    for (int k0 = 0; k0 < Cc; k0 += 16) {
        float4 a0 = *(const float4*)&w_ff[(size_t)(d0 + am) * Cc + k0 + kq];
        float4 a1 = *(const float4*)&w_ff[(size_t)(d0 + am) * Cc + k0 + kq + 4];
        As[kq + 0][am] = a0.x; As[kq + 1][am] = a0.y;
        As[kq + 2][am] = a0.z; As[kq + 3][am] = a0.w;
        As[kq + 4][am] = a1.x; As[kq + 5][am] = a1.y;
        As[kq + 6][am] = a1.z; As[kq + 7][am] = a1.w;
        const float* src = &yn[(size_t)(k0 + bk) * TV + p0 + bp];
        *(float4*)&Bs[bk][bp + 0]  = *(const float4*)&src[0];
        *(float4*)&Bs[bk][bp + 4]  = *(const float4*)&src[4];
        *(float4*)&Bs[bk][bp + 8]  = *(const float4*)&src[8];
        *(float4*)&Bs[bk][bp + 12] = *(const float4*)&src[12];
        __syncthreads();
#pragma unroll
        for (int k = 0; k < 16; k++) {
            float4 ra0 = *(float4*)&As[k][trow * 4];
            float4 ra1 = *(float4*)&As[k][32 + trow * 4];
            float4 rb0 = *(float4*)&Bs[k][tcol * 4];
            float4 rb1 = *(float4*)&Bs[k][64 + tcol * 4];
            float a_[8] = {ra0.x, ra0.y, ra0.z, ra0.w, ra1.x, ra1.y, ra1.z, ra1.w};
            float b_[8] = {rb0.x, rb0.y, rb0.z, rb0.w, rb1.x, rb1.y, rb1.z, rb1.w};
#pragma unroll
            for (int i = 0; i < 8; i++)
#pragma unroll
                for (int j = 0; j < 8; j++)
                    acc[i][j] = fmaf(a_[i], b_[j], acc[i][j]);
        }
        __syncthreads();
    }

    const float* xn = x + (size_t)n * Cc * TV;
#pragma unroll
    for (int h = 0; h < 2; h++)
#pragma unroll
        for (int i = 0; i < 4; i++) {
            const int d = d0 + h * 32 + trow * 4 + i;
            const int r = h * 4 + i;
            const float inv = gamma[d] * rsqrtf(var[d] + 1e-5f);
            const float add = (b_ff[d] - mean[d]) * inv + beta[d];
#pragma unroll
            for (int g = 0; g < 2; g++) {
                const size_t off = (size_t)d * TV + p0 + g * 64 + tcol * 4;
                float4 xv = *(const float4*)&xn[off];
                float z0 = xv.x + acc[r][g * 4 + 0] * inv + add;
                float z1 = xv.y + acc[r][g * 4 + 1] * inv + add;
                float z2 = xv.z + acc[r][g * 4 + 2] * inv + add;
                float z3 = xv.w + acc[r][g * 4 + 3] * inv + add;
                float4 o;
                o.x = z0 >= 0.f ? z0 : 0.1f * z0;
                o.y = z1 >= 0.f ? z1 : 0.1f * z1;
                o.z = z2 >= 0.f ? z2 : 0.1f * z2;
                o.w = z3 >= 0.f ? z3 : 0.1f * z3;
                *(float4*)&out[(size_t)n * Cc * TV + off] = o;
            }
        }
}

// ---------------------------------------------------------------------------
extern "C" void kernel_launch(void* const* d_in, const int* in_sizes, int n_in,
                              void* d_out, int out_size) {
    (void)in_sizes; (void)n_in; (void)out_size;
    const float* x     = (const float*)d_in[0];
    const float* w_in  = (const float*)d_in[1];
    const float* b_in  = (const float*)d_in[2];
    const float* w_ff  = (const float*)d_in[3];
    const float* b_ff  = (const float*)d_in[4];
    const float* gamma = (const float*)d_in[5];
    const float* beta  = (const float*)d_in[6];
    const float* mean  = (const float*)d_in[7];
    const float* var   = (const float*)d_in[8];
    float* out = (float*)d_out;

    k_qkv<<<dim3(TV / 128, C3 / 64, Nn), 128>>>(x, w_in, b_in);
    k_att<<<dim3(Tt / 128, Tt / 64, Nn * Ss), 128>>>();
    k_y  <<<dim3((MID * Vv) / 64, Tt / 128, Nn * Ss), 128>>>();
    k_ff <<<dim3(TV / 128, Cc / 64, Nn), 128>>>(x, w_ff, b_ff, gamma, beta,
                                                mean, var, out);
}

// round 3
// speedup vs baseline: 1.1971x; 1.0593x over previous
#include <cuda_runtime.h>
#include <math.h>
#include <stdint.h>

#define Nn   32
#define Cc   192
#define Tt   256
#define Vv   25
#define Ss   3
#define MID  64
#define TV   (Tt * Vv)      /* 6400 */
#define C3   (3 * Cc)       /* 576  */

// Scratch (static device arrays; allocation-free per harness rules)
__device__ float g_qkv[(size_t)Nn * C3 * TV];      // ~472 MB
__device__ float g_att[(size_t)Nn * Ss * Tt * Tt]; // ~25 MB
__device__ float g_y[(size_t)Nn * Cc * TV];        // ~157 MB

// ---------------------------------------------------------------------------
// TF32 helpers
// ---------------------------------------------------------------------------
__device__ __forceinline__ uint32_t f2tf32(float x) {
    uint32_t r;
    asm("cvt.rna.tf32.f32 %0, %1;" : "=r"(r) : "f"(x));
    return r;
}
__device__ __forceinline__ void mma_tf32(float* d, const uint32_t* a,
                                         uint32_t b0, uint32_t b1) {
    asm volatile(
        "mma.sync.aligned.m16n8k8.row.col.f32.tf32.tf32.f32 "
        "{%0,%1,%2,%3}, {%4,%5,%6,%7}, {%8,%9}, {%0,%1,%2,%3};"
        : "+f"(d[0]), "+f"(d[1]), "+f"(d[2]), "+f"(d[3])
        : "r"(a[0]), "r"(a[1]), "r"(a[2]), "r"(a[3]), "r"(b0), "r"(b1));
}

// smem strides (floats): stride mod 32 == 8 -> conflict-free fragment loads
#define SA 72    /* A: 16 k-rows x 64 m (+pad) */
#define SB 264   /* B: 16 k-rows x 256 n (+pad) */

// ---------------------------------------------------------------------------
// Shared tensor-core GEMM core:
//   acc[mt][nt][4] += sum_c  W[d0+.., c] * ACT[c, p0+..]
// W: [Md][192] row-major (c contiguous); ACT: [192][6400] (p contiguous).
// Block tile 64(M=d) x 256(N=p), BK=16, 128 threads = 4 warps (1x4),
// warp tile 64x64 (mt=4, nt=8). 3xTF32 hi/lo split (error ~1e-7).
// ---------------------------------------------------------------------------
__device__ __forceinline__ void gemm_core_tf32(
    const float* __restrict__ W, const float* __restrict__ ACT,
    int d0, int p0,
    uint32_t* Ahi, uint32_t* Alo, uint32_t* Bhi, uint32_t* Blo,
    float acc[4][8][4])
{
    const int tid  = threadIdx.x;
    const int warp = tid >> 5;
    const int lane = tid & 31;
    const int g    = lane >> 2;   // groupID (0..7)
    const int ltg  = lane & 3;    // thread-in-group (0..3)

    // A stage indices: thread -> (d row, k-quad)
    const int ad = tid >> 1;           // 0..63
    const int akq = (tid & 1) * 8;     // 0 or 8
    // B stage indices: thread -> (c row, 16-wide p chunk)
    const int bc = tid >> 4;           // 0..7 (+8 on 2nd pass)
    const int bp = (tid & 15) * 16;

#pragma unroll 1
    for (int k0 = 0; k0 < Cc; k0 += 16) {
        // ---- stage A (64 x 16), transpose + hi/lo split ----
        {
            const float* src = &W[(size_t)(d0 + ad) * Cc + k0 + akq];
            float4 w0 = *(const float4*)&src[0];
            float4 w1 = *(const float4*)&src[4];
            float v[8] = {w0.x, w0.y, w0.z, w0.w, w1.x, w1.y, w1.z, w1.w};
#pragma unroll
            for (int j = 0; j < 8; j++) {
                uint32_t hi = f2tf32(v[j]);
                float lof = v[j] - __uint_as_float(hi);
                Ahi[(akq + j) * SA + ad] = hi;
                Alo[(akq + j) * SA + ad] = f2tf32(lof);
            }
        }
        // ---- stage B (16 x 256), direct rows + hi/lo split ----
#pragma unroll
        for (int h = 0; h < 2; h++) {
            const int c = bc + h * 8;
            const float* src = &ACT[(size_t)(k0 + c) * TV + p0 + bp];
#pragma unroll
            for (int u = 0; u < 4; u++) {
                float4 bv = *(const float4*)&src[u * 4];
                uint4 hi, lo;
                hi.x = f2tf32(bv.x); lo.x = f2tf32(bv.x - __uint_as_float(hi.x));
                hi.y = f2tf32(bv.y); lo.y = f2tf32(bv.y - __uint_as_float(hi.y));
                hi.z = f2tf32(bv.z); lo.z = f2tf32(bv.z - __uint_as_float(hi.z));
                hi.w = f2tf32(bv.w); lo.w = f2tf32(bv.w - __uint_as_float(hi.w));
                *(uint4*)&Bhi[c * SB + bp + u * 4] = hi;
                *(uint4*)&Blo[c * SB + bp + u * 4] = lo;
            }
        }
        __syncthreads();

        // ---- compute 2 x k8 steps ----
#pragma unroll
        for (int k8 = 0; k8 < 16; k8 += 8) {
            uint32_t ahi[4][4], alo[4][4];
#pragma unroll
            for (int mt = 0; mt < 4; mt++) {
                const int m = mt * 16;
                const int r0 = (k8 + ltg) * SA, r1 = (k8 + ltg + 4) * SA;
                ahi[mt][0] = Ahi[r0 + m + g];
                ahi[mt][1] = Ahi[r0 + m + 8 + g];
                ahi[mt][2] = Ahi[r1 + m + g];
                ahi[mt][3] = Ahi[r1 + m + 8 + g];
                alo[mt][0] = Alo[r0 + m + g];
                alo[mt][1] = Alo[r0 + m + 8 + g];
                alo[mt][2] = Alo[r1 + m + g];
                alo[mt][3] = Alo[r1 + m + 8 + g];
            }
#pragma unroll
            for (int nt = 0; nt < 8; nt++) {
                const int nn = warp * 64 + nt * 8 + g;
                const int r0 = (k8 + ltg) * SB, r1 = (k8 + ltg + 4) * SB;
                uint32_t bhi0 = Bhi[r0 + nn], bhi1 = Bhi[r1 + nn];
                uint32_t blo0 = Blo[r0 + nn], blo1 = Blo[r1 + nn];
#pragma unroll
                for (int mt = 0; mt < 4; mt++) {
                    mma_tf32(acc[mt][nt], ahi[mt], bhi0, bhi1);
                    mma_tf32(acc[mt][nt], ahi[mt], blo0, blo1);
                    mma_tf32(acc[mt][nt], alo[mt], bhi0, bhi1);
                }
            }
        }
        __syncthreads();
    }
}

// ---------------------------------------------------------------------------
// Kernel 1: QKV projection via tensor cores.
// qkv[n][d][p] = sum_c w_in[d][c] * x[n][c][p] + b_in[d]
// ---------------------------------------------------------------------------
__global__ __launch_bounds__(128) void k_qkv(const float* __restrict__ x,
                                             const float* __restrict__ w_in,
                                             const float* __restrict__ b_in) {
    __shared__ uint32_t Ahi[16 * SA], Alo[16 * SA];
    __shared__ uint32_t Bhi[16 * SB], Blo[16 * SB];
    const int n  = blockIdx.z;
    const int d0 = blockIdx.y * 64;
    const int p0 = blockIdx.x * 256;
    const int tid = threadIdx.x;
    const int warp = tid >> 5, lane = tid & 31;
    const int g = lane >> 2, ltg = lane & 3;

    float acc[4][8][4];
#pragma unroll
    for (int mt = 0; mt < 4; mt++)
#pragma unroll
        for (int nt = 0; nt < 8; nt++)
#pragma unroll
            for (int e = 0; e < 4; e++) acc[mt][nt][e] = 0.f;

    gemm_core_tf32(w_in, x + (size_t)n * Cc * TV, d0, p0,
                   Ahi, Alo, Bhi, Blo, acc);

    float* out = g_qkv + (size_t)n * C3 * TV;
#pragma unroll
    for (int mt = 0; mt < 4; mt++) {
        const int r0 = d0 + mt * 16 + g;
        const int r1 = r0 + 8;
        const float bias0 = b_in[r0];
        const float bias1 = b_in[r1];
#pragma unroll
        for (int nt = 0; nt < 8; nt++) {
            const int col = p0 + warp * 64 + nt * 8 + ltg * 2;
            float2 v0 = make_float2(acc[mt][nt][0] + bias0,
                                    acc[mt][nt][1] + bias0);
            float2 v1 = make_float2(acc[mt][nt][2] + bias1,
                                    acc[mt][nt][3] + bias1);
            *(float2*)&out[(size_t)r0 * TV + col] = v0;
            *(float2*)&out[(size_t)r1 * TV + col] = v1;
        }
    }
}

// ---------------------------------------------------------------------------
// Kernel 4: FF + BN + residual + LeakyReLU via tensor cores.
// ---------------------------------------------------------------------------
__global__ __launch_bounds__(128) void k_ff(const float* __restrict__ x,
                                            const float* __restrict__ w_ff,
                                            const float* __restrict__ b_ff,
                                            const float* __restrict__ gamma,
                                            const float* __restrict__ beta,
                                            const float* __restrict__ mean,
                                            const float* __restrict__ var,
                                            float* __restrict__ out) {
    __shared__ uint32_t Ahi[16 * SA], Alo[16 * SA];
    __shared__ uint32_t Bhi[16 * SB], Blo[16 * SB];
    const int n  = blockIdx.z;
    const int d0 = blockIdx.y * 64;
    const int p0 = blockIdx.x * 256;
    const int tid = threadIdx.x;
    const int warp = tid >> 5, lane = tid & 31;
    const int g = lane >> 2, ltg = lane & 3;

    float acc[4][8][4];
#pragma unroll
    for (int mt = 0; mt < 4; mt++)
#pragma unroll
        for (int nt = 0; nt < 8; nt++)
#pragma unroll
            for (int e = 0; e < 4; e++) acc[mt][nt][e] = 0.f;

    gemm_core_tf32(w_ff, g_y + (size_t)n * Cc * TV, d0, p0,
                   Ahi, Alo, Bhi, Blo, acc);

    const float* xn = x + (size_t)n * Cc * TV;
    float* on = out + (size_t)n * Cc * TV;
#pragma unroll
    for (int mt = 0; mt < 4; mt++) {
        const int r0 = d0 + mt * 16 + g;
        const int r1 = r0 + 8;
        const float inv0 = gamma[r0] * rsqrtf(var[r0] + 1e-5f);
        const float add0 = (b_ff[r0] - mean[r0]) * inv0 + beta[r0];
        const float inv1 = gamma[r1] * rsqrtf(var[r1] + 1e-5f);
        const float add1 = (b_ff[r1] - mean[r1]) * inv1 + beta[r1];
#pragma unroll
        for (int nt = 0; nt < 8; nt++) {
            const int col = p0 + warp * 64 + nt * 8 + ltg * 2;
            float2 x0 = *(const float2*)&xn[(size_t)r0 * TV + col];
            float2 x1 = *(const float2*)&xn[(size_t)r1 * TV + col];
            float z0 = x0.x + acc[mt][nt][0] * inv0 + add0;
            float z1 = x0.y + acc[mt][nt][1] * inv0 + add0;
            float z2 = x1.x + acc[mt][nt][2] * inv1 + add1;
            float z3 = x1.y + acc[mt][nt][3] * inv1 + add1;
            float2 o0, o1;
            o0.x = z0 >= 0.f ? z0 : 0.1f * z0;
            o0.y = z1 >= 0.f ? z1 : 0.1f * z1;
            o1.x = z2 >= 0.f ? z2 : 0.1f * z2;
            o1.y = z3 >= 0.f ? z3 : 0.1f * z3;
            *(float2*)&on[(size_t)r0 * TV + col] = o0;
            *(float2*)&on[(size_t)r1 * TV + col] = o1;
        }
    }
}

// ---------------------------------------------------------------------------
// Kernel 2: attention scores (FFMA, unchanged from R2 — known good).
// ---------------------------------------------------------------------------
__global__ __launch_bounds__(128) void k_att() {
    __shared__ float Qs[25][68];
    __shared__ float Ks[25][136];
    const int ns = blockIdx.z;
    const int n = ns / 3, s = ns - 3 * n;
    const int t0 = blockIdx.y * 64;
    const int q0 = blockIdx.x * 128;
    const int tid  = threadIdx.x;
    const int trow = tid >> 4;
    const int tcol = tid & 15;

    const float* qbase = g_qkv + ((size_t)n * C3 + s * MID) * TV + (size_t)t0 * Vv;
    const float* kbase = g_qkv + ((size_t)n * C3 + Ss * MID + s * MID) * TV + (size_t)q0 * Vv;

    float acc[8][8] = {};

    for (int c = 0; c < MID; c++) {
        const float* qc = qbase + (size_t)c * TV;
        const float* kc = kbase + (size_t)c * TV;
        for (int idx = tid; idx < 64 * Vv; idx += 128) {
            const int t = idx / 25, v = idx - t * 25;
            Qs[v][t] = qc[idx];
        }
        for (int idx = tid; idx < 128 * Vv; idx += 128) {
            const int t = idx / 25, v = idx - t * 25;
            Ks[v][t] = kc[idx];
        }
        __syncthreads();
#pragma unroll
        for (int v = 0; v < 25; v++) {
            float4 ra0 = *(float4*)&Qs[v][trow * 4];
            float4 ra1 = *(float4*)&Qs[v][32 + trow * 4];
            float4 rb0 = *(float4*)&Ks[v][tcol * 4];
            float4 rb1 = *(float4*)&Ks[v][64 + tcol * 4];
            float a_[8] = {ra0.x, ra0.y, ra0.z, ra0.w, ra1.x, ra1.y, ra1.z, ra1.w};
            float b_[8] = {rb0.x, rb0.y, rb0.z, rb0.w, rb1.x, rb1.y, rb1.z, rb1.w};
#pragma unroll
            for (int i = 0; i < 8; i++)
#pragma unroll
                for (int j = 0; j < 8; j++)
                    acc[i][j] = fmaf(a_[i], b_[j], acc[i][j]);
        }
        __syncthreads();
    }

    const float scale = 1.0f / (float)(MID * Vv);
    float* att = g_att + (size_t)ns * Tt * Tt;
#pragma unroll
    for (int h = 0; h < 2; h++)
#pragma unroll
        for (int i = 0; i < 4; i++) {
            const int t = t0 + h * 32 + trow * 4 + i;
            const int r = h * 4 + i;
#pragma unroll
            for (int g2 = 0; g2 < 2; g2++) {
                float4 v = make_float4(tanhf(acc[r][g2 * 4 + 0] * scale),
                                       tanhf(acc[r][g2 * 4 + 1] * scale),
                                       tanhf(acc[r][g2 * 4 + 2] * scale),
                                       tanhf(acc[r][g2 * 4 + 3] * scale));
                *(float4*)&att[(size_t)t * Tt + q0 + g2 * 64 + tcol * 4] = v;
            }
        }
}

// ---------------------------------------------------------------------------
// Kernel 3: y = att @ V (FFMA, unchanged from R2 — known good).
// ---------------------------------------------------------------------------
__global__ __launch_bounds__(128) void k_y() {
    __shared__ float As[32][132];
    __shared__ float Bs[32][64];
    const int ns = blockIdx.z;
    const int n = ns / 3, s = ns - 3 * n;
    const int t0 = blockIdx.y * 128;
    const int j0 = blockIdx.x * 64;
    const int tid  = threadIdx.x;
    const int trow = tid >> 3;
    const int tcol = tid & 7;

    const float* att   = g_att + (size_t)ns * Tt * Tt;
    const float* vbase = g_qkv + ((size_t)n * C3 + 2 * Ss * MID + s * MID) * TV;

    float acc[8][8] = {};

    for (int qk = 0; qk < Tt; qk += 32) {
        const float* arow = &att[(size_t)(t0 + tid) * Tt + qk];
#pragma unroll
        for (int u = 0; u < 8; u++) {
            float4 v = *(const float4*)&arow[u * 4];
            As[u * 4 + 0][tid] = v.x; As[u * 4 + 1][tid] = v.y;
            As[u * 4 + 2][tid] = v.z; As[u * 4 + 3][tid] = v.w;
        }
#pragma unroll
        for (int l = 0; l < 16; l++) {
            const int idx = l * 128 + tid;
            const int q = idx >> 6, j = idx & 63;
            const int jj = j0 + j;
            const int c = jj / 25, v = jj - c * 25;
            Bs[q][j] = vbase[((size_t)c * Tt + qk + q) * Vv + v];
        }
        __syncthreads();
#pragma unroll
        for (int k = 0; k < 32; k++) {
            float4 ra0 = *(float4*)&As[k][trow * 4];
            float4 ra1 = *(float4*)&As[k][64 + trow * 4];
            float4 rb0 = *(float4*)&Bs[k][tcol * 4];
            float4 rb1 = *(float4*)&Bs[k][32 + tcol * 4];
            float a_[8] = {ra0.x, ra0.y, ra0.z, ra0.w, ra1.x, ra1.y, ra1.z, ra1.w};
            float b_[8] = {rb0.x, rb0.y, rb0.z, rb0.w, rb1.x, rb1.y, rb1.z, rb1.w};
#pragma unroll
            for (int i = 0; i < 8; i++)
#pragma unroll
                for (int j = 0; j < 8; j++)
                    acc[i][j] = fmaf(a_[i], b_[j], acc[i][j]);
        }
        __syncthreads();
    }

    float* yn = g_y + (size_t)n * Cc * TV;
#pragma unroll
    for (int h = 0; h < 2; h++)
#pragma unroll
        for (int i = 0; i < 4; i++) {
            const int t = t0 + h * 64 + trow * 4 + i;
            const int r = h * 4 + i;
#pragma unroll
            for (int g2 = 0; g2 < 2; g2++)
#pragma unroll
                for (int j = 0; j < 4; j++) {
                    const int jj = j0 + g2 * 32 + tcol * 4 + j;
                    const int c = jj / 25, v = jj - c * 25;
                    yn[((size_t)(s * MID + c) * Tt + t) * Vv + v] =
                        acc[r][g2 * 4 + j];
                }
        }
}

// ---------------------------------------------------------------------------
extern "C" void kernel_launch(void* const* d_in, const int* in_sizes, int n_in,
                              void* d_out, int out_size) {
    (void)in_sizes; (void)n_in; (void)out_size;
    const float* x     = (const float*)d_in[0];
    const float* w_in  = (const float*)d_in[1];
    const float* b_in  = (const float*)d_in[2];
    const float* w_ff  = (const float*)d_in[3];
    const float* b_ff  = (const float*)d_in[4];
    const float* gamma = (const float*)d_in[5];
    const float* beta  = (const float*)d_in[6];
    const float* mean  = (const float*)d_in[7];
    const float* var   = (const float*)d_in[8];
    float* out = (float*)d_out;

    k_qkv<<<dim3(TV / 256, C3 / 64, Nn), 128>>>(x, w_in, b_in);
    k_att<<<dim3(Tt / 128, Tt / 64, Nn * Ss), 128>>>();
    k_y  <<<dim3((MID * Vv) / 64, Tt / 128, Nn * Ss), 128>>>();
    k_ff <<<dim3(TV / 256, Cc / 64, Nn), 128>>>(x, w_ff, b_ff, gamma, beta,
                                                mean, var, out);
}

// round 4
// speedup vs baseline: 2.0325x; 1.6978x over previous
#include <cuda_runtime.h>
#include <math.h>
#include <stdint.h>

#define Nn   32
#define Cc   192
#define Tt   256
#define Vv   25
#define Ss   3
#define MID  64
#define TV   6400          /* T*V */
#define C3   576           /* 3*C */
#define KF   1600          /* MID*Vv flattened contraction for attention */

// Scratch (static device arrays; allocation-free per harness rules)
// Token-major qkv: [n][part(q/k/v)][s][t][c*25+v]
__device__ float g_tok[(size_t)Nn * 3 * Ss * Tt * KF];   // 472 MB
__device__ float g_att[(size_t)Nn * Ss * Tt * Tt];       // 25 MB  [ns][t][q]
__device__ float g_y[(size_t)Nn * Cc * TV];              // 157 MB [n][d][t*25+v]

// ---------------------------------------------------------------------------
// TF32 helpers
// ---------------------------------------------------------------------------
__device__ __forceinline__ uint32_t f2tf32(float x) {
    uint32_t r;
    asm("cvt.rna.tf32.f32 %0, %1;" : "=r"(r) : "f"(x));
    return r;
}
__device__ __forceinline__ void mma_tf32(float* d, const uint32_t* a,
                                         uint32_t b0, uint32_t b1) {
    asm volatile(
        "mma.sync.aligned.m16n8k8.row.col.f32.tf32.tf32.f32 "
        "{%0,%1,%2,%3}, {%4,%5,%6,%7}, {%8,%9}, {%0,%1,%2,%3};"
        : "+f"(d[0]), "+f"(d[1]), "+f"(d[2]), "+f"(d[3])
        : "r"(a[0]), "r"(a[1]), "r"(a[2]), "r"(a[3]), "r"(b0), "r"(b1));
}

// Compute one BK=16 chunk. As: [k][M] stride SAs, Bs: [k][N] stride SBs.
// Warp tile 32(m) x 64(n) at (m0, n0). acc[2][8][4].
// Strides SAs/SBs mod 32 == 8 -> conflict-free fragment loads.
template <int SAs, int SBs>
__device__ __forceinline__ void mma_chunk(const uint32_t* __restrict__ As,
                                          const uint32_t* __restrict__ Bs,
                                          float acc[2][8][4],
                                          int m0, int n0, int lane) {
    const int g = lane >> 2, ltg = lane & 3;
#pragma unroll
    for (int k8 = 0; k8 < 16; k8 += 8) {
        uint32_t a[2][4];
#pragma unroll
        for (int mt = 0; mt < 2; mt++) {
            const int m = m0 + mt * 16 + g;
            a[mt][0] = As[(k8 + ltg) * SAs + m];
            a[mt][1] = As[(k8 + ltg) * SAs + m + 8];
            a[mt][2] = As[(k8 + ltg + 4) * SAs + m];
            a[mt][3] = As[(k8 + ltg + 4) * SAs + m + 8];
        }
#pragma unroll
        for (int nt = 0; nt < 8; nt++) {
            const int nn = n0 + nt * 8 + g;
            const uint32_t b0 = Bs[(k8 + ltg) * SBs + nn];
            const uint32_t b1 = Bs[(k8 + ltg + 4) * SBs + nn];
#pragma unroll
            for (int mt = 0; mt < 2; mt++)
                mma_tf32(acc[mt][nt], a[mt], b0, b1);
        }
    }
}

// ---------------------------------------------------------------------------
// Kernel 1: QKV projection.  qkv[d][p] = sum_c w_in[d][c] * x[n][c][p] + b
// Block 64(d) x 256(p), BK=16, 256 threads, warps 2x4 of 32x64.
// Output scattered to token-major g_tok.
// ---------------------------------------------------------------------------
__global__ __launch_bounds__(256, 2) void k_qkv(const float* __restrict__ x,
                                                const float* __restrict__ w_in,
                                                const float* __restrict__ b_in) {
    __shared__ uint32_t As[16 * 72];
    __shared__ uint32_t Bs[16 * 264];
    const int n  = blockIdx.z;
    const int d0 = blockIdx.y * 64;
    const int p0 = blockIdx.x * 256;
    const int tid = threadIdx.x, warp = tid >> 5, lane = tid & 31;
    const int wm = warp >> 2, wn = warp & 3;
    const int g = lane >> 2, ltg = lane & 3;

    const float* xn = x + (size_t)n * Cc * TV;
    float acc[2][8][4] = {};

    const int ad = tid >> 2, akq = (tid & 3) * 4;   // A: 64 rows x 16k
    const int bc = tid >> 4, bp = (tid & 15) * 16;  // B: 16 rows x 256p

    for (int k0 = 0; k0 < Cc; k0 += 16) {
        float4 w4 = *(const float4*)&w_in[(size_t)(d0 + ad) * Cc + k0 + akq];
        As[(akq + 0) * 72 + ad] = f2tf32(w4.x);
        As[(akq + 1) * 72 + ad] = f2tf32(w4.y);
        As[(akq + 2) * 72 + ad] = f2tf32(w4.z);
        As[(akq + 3) * 72 + ad] = f2tf32(w4.w);
        const float* src = &xn[(size_t)(k0 + bc) * TV + p0 + bp];
#pragma unroll
        for (int u = 0; u < 4; u++) {
            float4 b4 = *(const float4*)&src[u * 4];
            uint4 t4;
            t4.x = f2tf32(b4.x); t4.y = f2tf32(b4.y);
            t4.z = f2tf32(b4.z); t4.w = f2tf32(b4.w);
            *(uint4*)&Bs[bc * 264 + bp + u * 4] = t4;
        }
        __syncthreads();
        mma_chunk<72, 264>(As, Bs, acc, wm * 32, wn * 64, lane);
        __syncthreads();
    }

    // epilogue: scatter to token-major layout
    const int part = d0 / Cc;
    const int s = (d0 % Cc) / MID;
    float* base = g_tok + (((size_t)(n * 3 + part) * Ss + s) * Tt) * KF;
#pragma unroll
    for (int mt = 0; mt < 2; mt++)
#pragma unroll
        for (int half = 0; half < 2; half++) {
            const int c = wm * 32 + mt * 16 + g + half * 8;  // 0..63
            const float bias = b_in[d0 + c];
#pragma unroll
            for (int nt = 0; nt < 8; nt++)
#pragma unroll
                for (int e = 0; e < 2; e++) {
                    const int p = p0 + wn * 64 + nt * 8 + ltg * 2 + e;
                    const int t = p / 25, v = p - t * 25;
                    base[(size_t)t * KF + c * 25 + v] =
                        acc[mt][nt][half * 2 + e] + bias;
                }
        }
}

// ---------------------------------------------------------------------------
// Kernel 2: att[ns][t][q] = tanh( (1/1600) * sum_k Q_t[t][k] * K_t[q][k] )
// Per (n,s): M=64(t tile) x N=256(q, full) x K=1600.
// ---------------------------------------------------------------------------
__global__ __launch_bounds__(256, 2) void k_att() {
    __shared__ uint32_t As[16 * 72];    // [k][t]
    __shared__ uint32_t Bs[16 * 264];   // [k][q]
    const int ns = blockIdx.z;
    const int n = ns / 3, s = ns - 3 * n;
    const int t0 = blockIdx.y * 64;
    const int tid = threadIdx.x, warp = tid >> 5, lane = tid & 31;
    const int wm = warp >> 2, wn = warp & 3;
    const int g = lane >> 2, ltg = lane & 3;

    const float* Qb = g_tok + (((size_t)(n * 3 + 0) * Ss + s) * Tt) * KF;
    const float* Kb = g_tok + (((size_t)(n * 3 + 1) * Ss + s) * Tt) * KF;

    float acc[2][8][4] = {};

    const int at = tid >> 2, ak4 = (tid & 3) * 4;   // A: 64 t x 16 k

    for (int k0 = 0; k0 < KF; k0 += 16) {
        float4 q4 = *(const float4*)&Qb[(size_t)(t0 + at) * KF + k0 + ak4];
        As[(ak4 + 0) * 72 + at] = f2tf32(q4.x);
        As[(ak4 + 1) * 72 + at] = f2tf32(q4.y);
        As[(ak4 + 2) * 72 + at] = f2tf32(q4.z);
        As[(ak4 + 3) * 72 + at] = f2tf32(q4.w);
#pragma unroll
        for (int step = 0; step < 4; step++) {
            const int id = step * 256 + tid;
            const int q = id >> 2, k4 = (id & 3) * 4;
            float4 b4 = *(const float4*)&Kb[(size_t)q * KF + k0 + k4];
            Bs[(k4 + 0) * 264 + q] = f2tf32(b4.x);
            Bs[(k4 + 1) * 264 + q] = f2tf32(b4.y);
            Bs[(k4 + 2) * 264 + q] = f2tf32(b4.z);
            Bs[(k4 + 3) * 264 + q] = f2tf32(b4.w);
        }
        __syncthreads();
        mma_chunk<72, 264>(As, Bs, acc, wm * 32, wn * 64, lane);
        __syncthreads();
    }

    const float scale = 1.0f / (float)KF;
    float* arow = g_att + (size_t)ns * Tt * Tt;
#pragma unroll
    for (int mt = 0; mt < 2; mt++)
#pragma unroll
        for (int half = 0; half < 2; half++) {
            const int t = t0 + wm * 32 + mt * 16 + g + half * 8;
#pragma unroll
            for (int nt = 0; nt < 8; nt++) {
                const int q = wn * 64 + nt * 8 + ltg * 2;
                float2 o;
                o.x = tanhf(acc[mt][nt][half * 2 + 0] * scale);
                o.y = tanhf(acc[mt][nt][half * 2 + 1] * scale);
                *(float2*)&arow[(size_t)t * Tt + q] = o;
            }
        }
}

// ---------------------------------------------------------------------------
// Kernel 3: y[t][j] = sum_q att[t][q] * V_t[q][j],  j = c*25+v (1600 wide)
// Per (n,s): M=256(t, full) x N=64(j tile) x K=256(q).
// 8 warps stacked along M (warp tile 32x64).
// ---------------------------------------------------------------------------
__global__ __launch_bounds__(256, 2) void k_y() {
    __shared__ uint32_t As[16 * 264];   // [k=q][t]
    __shared__ uint32_t Bs[16 * 72];    // [k=q][j]
    const int ns = blockIdx.z;
    const int n = ns / 3, s = ns - 3 * n;
    const int j0 = blockIdx.x * 64;
    const int tid = threadIdx.x, warp = tid >> 5, lane = tid & 31;
    const int g = lane >> 2, ltg = lane & 3;

    const float* att = g_att + (size_t)ns * Tt * Tt;
    const float* Vb  = g_tok + (((size_t)(n * 3 + 2) * Ss + s) * Tt) * KF;

    float acc[2][8][4] = {};

    const int bq = tid >> 4, bj = (tid & 15) * 4;   // B: 16 q x 64 j

    for (int k0 = 0; k0 < Tt; k0 += 16) {
        // A: transpose-stage att[t][k0..k0+16) -> As[k][t], 1024 f4
#pragma unroll
        for (int step = 0; step < 4; step++) {
            const int id = step * 256 + tid;
            const int t = id >> 2, k4 = (id & 3) * 4;
            float4 a4 = *(const float4*)&att[(size_t)t * Tt + k0 + k4];
            As[(k4 + 0) * 264 + t] = f2tf32(a4.x);
            As[(k4 + 1) * 264 + t] = f2tf32(a4.y);
            As[(k4 + 2) * 264 + t] = f2tf32(a4.z);
            As[(k4 + 3) * 264 + t] = f2tf32(a4.w);
        }
        // B: direct copy V_t[k0+q][j0..j0+64)
        {
            float4 b4 = *(const float4*)&Vb[(size_t)(k0 + bq) * KF + j0 + bj];
            uint4 t4;
            t4.x = f2tf32(b4.x); t4.y = f2tf32(b4.y);
            t4.z = f2tf32(b4.z); t4.w = f2tf32(b4.w);
            *(uint4*)&Bs[bq * 72 + bj] = t4;
        }
        __syncthreads();
        mma_chunk<264, 72>(As, Bs, acc, warp * 32, 0, lane);
        __syncthreads();
    }

    float* yb = g_y + (size_t)n * Cc * TV + (size_t)(s * MID) * TV;
#pragma unroll
    for (int mt = 0; mt < 2; mt++)
#pragma unroll
        for (int half = 0; half < 2; half++) {
            const int t = warp * 32 + mt * 16 + g + half * 8;
#pragma unroll
            for (int nt = 0; nt < 8; nt++)
#pragma unroll
                for (int e = 0; e < 2; e++) {
                    const int j = j0 + nt * 8 + ltg * 2 + e;
                    const int c = j / 25, v = j - c * 25;
                    yb[(size_t)c * TV + t * 25 + v] =
                        acc[mt][nt][half * 2 + e];
                }
        }
}

// ---------------------------------------------------------------------------
// Kernel 4: FF + BN + residual + LeakyReLU.
// Block 64(d) x 256(p), BK=16, fused epilogue.
// ---------------------------------------------------------------------------
__global__ __launch_bounds__(256, 2) void k_ff(const float* __restrict__ x,
                                               const float* __restrict__ w_ff,
                                               const float* __restrict__ b_ff,
                                               const float* __restrict__ gamma,
                                               const float* __restrict__ beta,
                                               const float* __restrict__ mean,
                                               const float* __restrict__ var,
                                               float* __restrict__ out) {
    __shared__ uint32_t As[16 * 72];
    __shared__ uint32_t Bs[16 * 264];
    const int n  = blockIdx.z;
    const int d0 = blockIdx.y * 64;
    const int p0 = blockIdx.x * 256;
    const int tid = threadIdx.x, warp = tid >> 5, lane = tid & 31;
    const int wm = warp >> 2, wn = warp & 3;
    const int g = lane >> 2, ltg = lane & 3;

    const float* yn = g_y + (size_t)n * Cc * TV;
    float acc[2][8][4] = {};

    const int ad = tid >> 2, akq = (tid & 3) * 4;
    const int bc = tid >> 4, bp = (tid & 15) * 16;

    for (int k0 = 0; k0 < Cc; k0 += 16) {
        float4 w4 = *(const float4*)&w_ff[(size_t)(d0 + ad) * Cc + k0 + akq];
        As[(akq + 0) * 72 + ad] = f2tf32(w4.x);
        As[(akq + 1) * 72 + ad] = f2tf32(w4.y);
        As[(akq + 2) * 72 + ad] = f2tf32(w4.z);
        As[(akq + 3) * 72 + ad] = f2tf32(w4.w);
        const float* src = &yn[(size_t)(k0 + bc) * TV + p0 + bp];
#pragma unroll
        for (int u = 0; u < 4; u++) {
            float4 b4 = *(const float4*)&src[u * 4];
            uint4 t4;
            t4.x = f2tf32(b4.x); t4.y = f2tf32(b4.y);
            t4.z = f2tf32(b4.z); t4.w = f2tf32(b4.w);
            *(uint4*)&Bs[bc * 264 + bp + u * 4] = t4;
        }
        __syncthreads();
        mma_chunk<72, 264>(As, Bs, acc, wm * 32, wn * 64, lane);
        __syncthreads();
    }

    const float* xn = x + (size_t)n * Cc * TV;
    float* on = out + (size_t)n * Cc * TV;
#pragma unroll
    for (int mt = 0; mt < 2; mt++)
#pragma unroll
        for (int half = 0; half < 2; half++) {
            const int d = d0 + wm * 32 + mt * 16 + g + half * 8;
            const float inv = gamma[d] * rsqrtf(var[d] + 1e-5f);
            const float add = (b_ff[d] - mean[d]) * inv + beta[d];
#pragma unroll
            for (int nt = 0; nt < 8; nt++) {
                const int p = p0 + wn * 64 + nt * 8 + ltg * 2;
                const size_t off = (size_t)d * TV + p;
                float2 xv = *(const float2*)&xn[off];
                float z0 = xv.x + acc[mt][nt][half * 2 + 0] * inv + add;
                float z1 = xv.y + acc[mt][nt][half * 2 + 1] * inv + add;
                float2 o;
                o.x = z0 >= 0.f ? z0 : 0.1f * z0;
                o.y = z1 >= 0.f ? z1 : 0.1f * z1;
                *(float2*)&on[off] = o;
            }
        }
}

// ---------------------------------------------------------------------------
extern "C" void kernel_launch(void* const* d_in, const int* in_sizes, int n_in,
                              void* d_out, int out_size) {
    (void)in_sizes; (void)n_in; (void)out_size;
    const float* x     = (const float*)d_in[0];
    const float* w_in  = (const float*)d_in[1];
    const float* b_in  = (const float*)d_in[2];
    const float* w_ff  = (const float*)d_in[3];
    const float* b_ff  = (const float*)d_in[4];
    const float* gamma = (const float*)d_in[5];
    const float* beta  = (const float*)d_in[6];
    const float* mean  = (const float*)d_in[7];
    const float* var   = (const float*)d_in[8];
    float* out = (float*)d_out;

    k_qkv<<<dim3(TV / 256, C3 / 64, Nn), 256>>>(x, w_in, b_in);
    k_att<<<dim3(1, Tt / 64, Nn * Ss), 256>>>();
    k_y  <<<dim3(KF / 64, 1, Nn * Ss), 256>>>();
    k_ff <<<dim3(TV / 256, Cc / 64, Nn), 256>>>(x, w_ff, b_ff, gamma, beta,
                                                mean, var, out);
}

// round 5
// speedup vs baseline: 3.3681x; 1.6572x over previous
#include <cuda_runtime.h>
#include <math.h>
#include <stdint.h>

#define Nn   32
#define Cc   192
#define Tt   256
#define Vv   25
#define Ss   3
#define MID  64
#define TV   6400          /* T*V */
#define C3   576           /* 3*C */
#define KF   1600          /* MID*Vv flattened contraction for attention */

// Scratch (static device arrays; allocation-free per harness rules)
__device__ float g_tok[(size_t)Nn * 3 * Ss * Tt * KF];   // token-major qkv
__device__ float g_att[(size_t)Nn * Ss * Tt * Tt];       // [ns][t][q]
__device__ float g_y[(size_t)Nn * Cc * TV];              // [n][d][t*25+v]

// ---------------------------------------------------------------------------
// helpers
// ---------------------------------------------------------------------------
__device__ __forceinline__ uint32_t f2tf32(float x) {
    uint32_t r;
    asm("cvt.rna.tf32.f32 %0, %1;" : "=r"(r) : "f"(x));
    return r;
}
__device__ __forceinline__ void mma_tf32(float* d, const uint32_t* a,
                                         uint32_t b0, uint32_t b1) {
    asm volatile(
        "mma.sync.aligned.m16n8k8.row.col.f32.tf32.tf32.f32 "
        "{%0,%1,%2,%3}, {%4,%5,%6,%7}, {%8,%9}, {%0,%1,%2,%3};"
        : "+f"(d[0]), "+f"(d[1]), "+f"(d[2]), "+f"(d[3])
        : "r"(a[0]), "r"(a[1]), "r"(a[2]), "r"(a[3]), "r"(b0), "r"(b1));
}
__device__ __forceinline__ uint32_t smem_u32(const void* p) {
    return (uint32_t)__cvta_generic_to_shared(p);
}
__device__ __forceinline__ void cp16(uint32_t dst, const void* src) {
    asm volatile("cp.async.cg.shared.global [%0], [%1], 16;"
                 :: "r"(dst), "l"(src));
}
#define CP_COMMIT() asm volatile("cp.async.commit_group;")
#define CP_WAIT1()  asm volatile("cp.async.wait_group 1;" ::: "memory")

// A tiles: [row m][k] XOR-16 layout: element (m,k) at  m*16 + (k ^ 4*((m>>1)&3))
// B [k][n] tiles: row stride SBN (264 or 72), plain.
// Fragment math (warp tile 32m x 64n, acc[2][8][4]):

// A:[m][k]-xor16, B:[k][n]-SBN
template <int SBN>
__device__ __forceinline__ void mma_AkBn(const float* __restrict__ As,
                                         const float* __restrict__ Bs,
                                         float acc[2][8][4],
                                         int m0, int n0, int g, int ltg) {
    const int xk = 4 * ((g >> 1) & 3);
#pragma unroll
    for (int k8 = 0; k8 < 16; k8 += 8) {
        const int ka = (k8 + ltg) ^ xk;
        const int kb = (k8 + ltg + 4) ^ xk;
        uint32_t a[2][4];
#pragma unroll
        for (int mt = 0; mt < 2; mt++) {
            const float* Ar = As + (m0 + mt * 16 + g) * 16;
            a[mt][0] = f2tf32(Ar[ka]);
            a[mt][1] = f2tf32(Ar[128 + ka]);   // row m+8
            a[mt][2] = f2tf32(Ar[kb]);
            a[mt][3] = f2tf32(Ar[128 + kb]);
        }
#pragma unroll
        for (int nt = 0; nt < 8; nt++) {
            const int nn = n0 + nt * 8 + g;
            const uint32_t b0 = f2tf32(Bs[(k8 + ltg) * SBN + nn]);
            const uint32_t b1 = f2tf32(Bs[(k8 + ltg + 4) * SBN + nn]);
            mma_tf32(acc[0][nt], a[0], b0, b1);
            mma_tf32(acc[1][nt], a[1], b0, b1);
        }
    }
}

// A:[m][k]-xor16, B:[n][k]-xor16  (xor factor (n>>1)&3 == (g>>1)&3, same xk)
__device__ __forceinline__ void mma_AkBk(const float* __restrict__ As,
                                         const float* __restrict__ Bs,
                                         float acc[2][8][4],
                                         int m0, int n0, int g, int ltg) {
    const int xk = 4 * ((g >> 1) & 3);
#pragma unroll
    for (int k8 = 0; k8 < 16; k8 += 8) {
        const int ka = (k8 + ltg) ^ xk;
        const int kb = (k8 + ltg + 4) ^ xk;
        uint32_t a[2][4];
#pragma unroll
        for (int mt = 0; mt < 2; mt++) {
            const float* Ar = As + (m0 + mt * 16 + g) * 16;
            a[mt][0] = f2tf32(Ar[ka]);
            a[mt][1] = f2tf32(Ar[128 + ka]);
            a[mt][2] = f2tf32(Ar[kb]);
            a[mt][3] = f2tf32(Ar[128 + kb]);
        }
#pragma unroll
        for (int nt = 0; nt < 8; nt++) {
            const float* Br = Bs + (n0 + nt * 8 + g) * 16;
            const uint32_t b0 = f2tf32(Br[ka]);
            const uint32_t b1 = f2tf32(Br[kb]);
            mma_tf32(acc[0][nt], a[0], b0, b1);
            mma_tf32(acc[1][nt], a[1], b0, b1);
        }
    }
}

// ---------------------------------------------------------------------------
// Kernel 1: QKV projection. Block 64(d) x 256(p), BK=16, double-buffered.
// ---------------------------------------------------------------------------
__global__ __launch_bounds__(256, 2) void k_qkv(const float* __restrict__ x,
                                                const float* __restrict__ w_in,
                                                const float* __restrict__ b_in) {
    __shared__ __align__(16) float As[2][64 * 16];
    __shared__ __align__(16) float Bs[2][16 * 264];
    const int n  = blockIdx.z;
    const int d0 = blockIdx.y * 64;
    const int p0 = blockIdx.x * 256;
    const int tid = threadIdx.x, warp = tid >> 5, lane = tid & 31;
    const int wm = warp >> 2, wn = warp & 3;
    const int g = lane >> 2, ltg = lane & 3;

    const float* xn = x + (size_t)n * Cc * TV;

    const int ar = tid >> 2, au = tid & 3;          // A: row, granule
    const int axc = 4 * (au ^ ((ar >> 1) & 3));     // A dst col (xor)
    const int br = tid >> 4, bc4 = (tid & 15) * 4;  // B: row, col base

    auto stage = [&](int buf, int k0) {
        cp16(smem_u32(&As[buf][ar * 16 + axc]),
             &w_in[(size_t)(d0 + ar) * Cc + k0 + au * 4]);
        const float* src = &xn[(size_t)(k0 + br) * TV + p0 + bc4];
        float* dst = &Bs[buf][br * 264 + bc4];
#pragma unroll
        for (int u = 0; u < 4; u++)
            cp16(smem_u32(dst + u * 64), src + u * 64);
    };

    float acc[2][8][4] = {};
    stage(0, 0);
    CP_COMMIT();
    const int NC = Cc / 16;
    for (int c = 0; c < NC; c++) {
        if (c + 1 < NC) stage((c + 1) & 1, (c + 1) * 16);
        CP_COMMIT();
        CP_WAIT1();
        __syncthreads();
        mma_AkBn<264>(As[c & 1], Bs[c & 1], acc, wm * 32, wn * 64, g, ltg);
        __syncthreads();
    }

    // epilogue: scatter to token-major layout
    const int part = d0 / Cc;
    const int s = (d0 % Cc) / MID;
    float* base = g_tok + (((size_t)(n * 3 + part) * Ss + s) * Tt) * KF;
#pragma unroll
    for (int mt = 0; mt < 2; mt++)
#pragma unroll
        for (int half = 0; half < 2; half++) {
            const int cch = wm * 32 + mt * 16 + g + half * 8;
            const float bias = b_in[d0 + cch];
#pragma unroll
            for (int nt = 0; nt < 8; nt++)
#pragma unroll
                for (int e = 0; e < 2; e++) {
                    const int p = p0 + wn * 64 + nt * 8 + ltg * 2 + e;
                    const int t = p / 25, v = p - t * 25;
                    base[(size_t)t * KF + cch * 25 + v] =
                        acc[mt][nt][half * 2 + e] + bias;
                }
        }
}

// ---------------------------------------------------------------------------
// Kernel 2: att = tanh(Q K^T / 1600). Block 64(t) x 256(q), K=1600, BK=16.
// ---------------------------------------------------------------------------
__global__ __launch_bounds__(256, 2) void k_att() {
    __shared__ __align__(16) float As[2][64 * 16];
    __shared__ __align__(16) float Bs[2][256 * 16];
    const int ns = blockIdx.z;
    const int n = ns / 3, s = ns - 3 * n;
    const int t0 = blockIdx.y * 64;
    const int tid = threadIdx.x, warp = tid >> 5, lane = tid & 31;
    const int wm = warp >> 2, wn = warp & 3;
    const int g = lane >> 2, ltg = lane & 3;

    const float* Qb = g_tok + (((size_t)(n * 3 + 0) * Ss + s) * Tt) * KF;
    const float* Kb = g_tok + (((size_t)(n * 3 + 1) * Ss + s) * Tt) * KF;

    const int ar = tid >> 2, au = tid & 3;
    const int axc = 4 * (au ^ ((ar >> 1) & 3));

    auto stage = [&](int buf, int k0) {
        cp16(smem_u32(&As[buf][ar * 16 + axc]),
             &Qb[(size_t)(t0 + ar) * KF + k0 + au * 4]);
#pragma unroll
        for (int i = 0; i < 4; i++) {
            const int q = ar + 64 * i;
            cp16(smem_u32(&Bs[buf][q * 16 + axc]),
                 &Kb[(size_t)q * KF + k0 + au * 4]);
        }
    };

    float acc[2][8][4] = {};
    stage(0, 0);
    CP_COMMIT();
    const int NC = KF / 16;
    for (int c = 0; c < NC; c++) {
        if (c + 1 < NC) stage((c + 1) & 1, (c + 1) * 16);
        CP_COMMIT();
        CP_WAIT1();
        __syncthreads();
        mma_AkBk(As[c & 1], Bs[c & 1], acc, wm * 32, wn * 64, g, ltg);
        __syncthreads();
    }

    const float scale = 1.0f / (float)KF;
    float* arow = g_att + (size_t)ns * Tt * Tt;
#pragma unroll
    for (int mt = 0; mt < 2; mt++)
#pragma unroll
        for (int half = 0; half < 2; half++) {
            const int t = t0 + wm * 32 + mt * 16 + g + half * 8;
#pragma unroll
            for (int nt = 0; nt < 8; nt++) {
                const int q = wn * 64 + nt * 8 + ltg * 2;
                float2 o;
                o.x = tanhf(acc[mt][nt][half * 2 + 0] * scale);
                o.y = tanhf(acc[mt][nt][half * 2 + 1] * scale);
                *(float2*)&arow[(size_t)t * Tt + q] = o;
            }
        }
}

// ---------------------------------------------------------------------------
// Kernel 3: y = att @ V_t. Block 256(t, 8 warps stacked) x 64(j), K=256.
// ---------------------------------------------------------------------------
__global__ __launch_bounds__(256, 2) void k_y() {
    __shared__ __align__(16) float As[2][256 * 16];
    __shared__ __align__(16) float Bs[2][16 * 72];
    const int ns = blockIdx.z;
    const int n = ns / 3, s = ns - 3 * n;
    const int j0 = blockIdx.x * 64;
    const int tid = threadIdx.x, warp = tid >> 5, lane = tid & 31;
    const int g = lane >> 2, ltg = lane & 3;

    const float* att = g_att + (size_t)ns * Tt * Tt;
    const float* Vb  = g_tok + (((size_t)(n * 3 + 2) * Ss + s) * Tt) * KF;

    const int ar = tid >> 2, au = tid & 3;
    const int axc = 4 * (au ^ ((ar >> 1) & 3));
    const int br = tid >> 4, bc4 = (tid & 15) * 4;

    auto stage = [&](int buf, int k0) {
#pragma unroll
        for (int i = 0; i < 4; i++) {
            const int t = ar + 64 * i;
            cp16(smem_u32(&As[buf][t * 16 + axc]),
                 &att[(size_t)t * Tt + k0 + au * 4]);
        }
        cp16(smem_u32(&Bs[buf][br * 72 + bc4]),
             &Vb[(size_t)(k0 + br) * KF + j0 + bc4]);
    };

    float acc[2][8][4] = {};
    stage(0, 0);
    CP_COMMIT();
    const int NC = Tt / 16;
    for (int c = 0; c < NC; c++) {
        if (c + 1 < NC) stage((c + 1) & 1, (c + 1) * 16);
        CP_COMMIT();
        CP_WAIT1();
        __syncthreads();
        mma_AkBn<72>(As[c & 1], Bs[c & 1], acc, warp * 32, 0, g, ltg);
        __syncthreads();
    }

    float* yb = g_y + (size_t)n * Cc * TV + (size_t)(s * MID) * TV;
#pragma unroll
    for (int mt = 0; mt < 2; mt++)
#pragma unroll
        for (int half = 0; half < 2; half++) {
            const int t = warp * 32 + mt * 16 + g + half * 8;
#pragma unroll
            for (int nt = 0; nt < 8; nt++)
#pragma unroll
                for (int e = 0; e < 2; e++) {
                    const int j = j0 + nt * 8 + ltg * 2 + e;
                    const int cch = j / 25, v = j - cch * 25;
                    yb[(size_t)cch * TV + t * 25 + v] =
                        acc[mt][nt][half * 2 + e];
                }
        }
}

// ---------------------------------------------------------------------------
// Kernel 4: FF + BN + residual + LeakyReLU. Block 64(d) x 256(p), BK=16.
// ---------------------------------------------------------------------------
__global__ __launch_bounds__(256, 2) void k_ff(const float* __restrict__ x,
                                               const float* __restrict__ w_ff,
                                               const float* __restrict__ b_ff,
                                               const float* __restrict__ gamma,
                                               const float* __restrict__ beta,
                                               const float* __restrict__ mean,
                                               const float* __restrict__ var,
                                               float* __restrict__ out) {
    __shared__ __align__(16) float As[2][64 * 16];
    __shared__ __align__(16) float Bs[2][16 * 264];
    const int n  = blockIdx.z;
    const int d0 = blockIdx.y * 64;
    const int p0 = blockIdx.x * 256;
    const int tid = threadIdx.x, warp = tid >> 5, lane = tid & 31;
    const int wm = warp >> 2, wn = warp & 3;
    const int g = lane >> 2, ltg = lane & 3;

    const float* yn = g_y + (size_t)n * Cc * TV;

    const int ar = tid >> 2, au = tid & 3;
    const int axc = 4 * (au ^ ((ar >> 1) & 3));
    const int br = tid >> 4, bc4 = (tid & 15) * 4;

    auto stage = [&](int buf, int k0) {
        cp16(smem_u32(&As[buf][ar * 16 + axc]),
             &w_ff[(size_t)(d0 + ar) * Cc + k0 + au * 4]);
        const float* src = &yn[(size_t)(k0 + br) * TV + p0 + bc4];
        float* dst = &Bs[buf][br * 264 + bc4];
#pragma unroll
        for (int u = 0; u < 4; u++)
            cp16(smem_u32(dst + u * 64), src + u * 64);
    };

    float acc[2][8][4] = {};
    stage(0, 0);
    CP_COMMIT();
    const int NC = Cc / 16;
    for (int c = 0; c < NC; c++) {
        if (c + 1 < NC) stage((c + 1) & 1, (c + 1) * 16);
        CP_COMMIT();
        CP_WAIT1();
        __syncthreads();
        mma_AkBn<264>(As[c & 1], Bs[c & 1], acc, wm * 32, wn * 64, g, ltg);
        __syncthreads();
    }

    const float* xn = x + (size_t)n * Cc * TV;
    float* on = out + (size_t)n * Cc * TV;
#pragma unroll
    for (int mt = 0; mt < 2; mt++)
#pragma unroll
        for (int half = 0; half < 2; half++) {
            const int d = d0 + wm * 32 + mt * 16 + g + half * 8;
            const float inv = gamma[d] * rsqrtf(var[d] + 1e-5f);
            const float add = (b_ff[d] - mean[d]) * inv + beta[d];
#pragma unroll
            for (int nt = 0; nt < 8; nt++) {
                const int p = p0 + wn * 64 + nt * 8 + ltg * 2;
                const size_t off = (size_t)d * TV + p;
                float2 xv = *(const float2*)&xn[off];
                float z0 = xv.x + acc[mt][nt][half * 2 + 0] * inv + add;
                float z1 = xv.y + acc[mt][nt][half * 2 + 1] * inv + add;
                float2 o;
                o.x = z0 >= 0.f ? z0 : 0.1f * z0;
                o.y = z1 >= 0.f ? z1 : 0.1f * z1;
                *(float2*)&on[off] = o;
            }
        }
}

// ---------------------------------------------------------------------------
extern "C" void kernel_launch(void* const* d_in, const int* in_sizes, int n_in,
                              void* d_out, int out_size) {
    (void)in_sizes; (void)n_in; (void)out_size;
    const float* x     = (const float*)d_in[0];
    const float* w_in  = (const float*)d_in[1];
    const float* b_in  = (const float*)d_in[2];
    const float* w_ff  = (const float*)d_in[3];
    const float* b_ff  = (const float*)d_in[4];
    const float* gamma = (const float*)d_in[5];
    const float* beta  = (const float*)d_in[6];
    const float* mean  = (const float*)d_in[7];
    const float* var   = (const float*)d_in[8];
    float* out = (float*)d_out;

    k_qkv<<<dim3(TV / 256, C3 / 64, Nn), 256>>>(x, w_in, b_in);
    k_att<<<dim3(1, Tt / 64, Nn * Ss), 256>>>();
    k_y  <<<dim3(KF / 64, 1, Nn * Ss), 256>>>();
    k_ff <<<dim3(TV / 256, Cc / 64, Nn), 256>>>(x, w_ff, b_ff, gamma, beta,
                                                mean, var, out);
}